// round 15
// baseline (speedup 1.0000x reference)
#include <cuda_runtime.h>
#include <cuda_bf16.h>

#define NTHREADS 128
#define NCOLS 8              // columns per thread (contiguous): 128*8 = 1024
#define NQ 1024
#define NB 8
#define INFV 1e9f
#define BIGF 1e18f
#define NWARP (NTHREADS / 32)
#define QMASK 2047
#define TAGM 0x1FFFFFu       // 21-bit step tag

__device__ float g_partial[NB];
__device__ int   g_done = 0;                  // self-resetting completion counter

__device__ __forceinline__ float fsqrt_approx(float x) {
    float r; asm("sqrt.approx.f32 %0, %1;" : "=f"(r) : "f"(x)); return r;
}
__device__ __forceinline__ unsigned fmap(float x) {
    unsigned u = __float_as_uint(x);
    return (u & 0x80000000u) ? ~u : (u | 0x80000000u);
}
__device__ __forceinline__ float funmap(unsigned m) {
    unsigned u = (m & 0x80000000u) ? (m & 0x7fffffffu) : ~m;
    return __uint_as_float(u);
}

__global__ void __launch_bounds__(NTHREADS, 1)
emd_hungarian_kernel(const float* __restrict__ S1, const float* __restrict__ S2,
                     float* __restrict__ out) {
    const int b = blockIdx.x;
    const int t = threadIdx.x;
    const int lane = t & 31;
    const int warp = t >> 5;
    const int jbase = t * NCOLS + 1;          // first owned column (1-based)

    __shared__ float4 s_pt4[NQ + 1];          // row -> {x, y, z, u}
    __shared__ int    s_p[NQ + 1];            // col -> matched row (0 = free)
    __shared__ int    s_way[NQ + 1];
    __shared__ int    s_rowused[NQ + 1];
    __shared__ int    s_queue[QMASK + 1];
    __shared__ volatile unsigned long long s_key[2][NWARP];  // tagged argmin keys
    __shared__ unsigned long long s_t2[NWARP][2];
    __shared__ int    s_nexti, s_takej;
    __shared__ float  s_vadj;
    __shared__ float  s_acc[NWARP];

    for (int r = t; r < NQ; r += NTHREADS) {
        const float* p1 = S1 + ((size_t)b * NQ + r) * 3;
        s_pt4[r + 1] = make_float4(p1[0], p1[1], p1[2], 0.0f);
    }
    for (int idx = t; idx <= NQ; idx += NTHREADS) {
        s_p[idx] = 0; s_rowused[idx] = 0;
    }
    if (t < 2 * NWARP)
        ((volatile unsigned long long*)s_key)[t] = ~0ull;  // tag=max: never matches

    float v[NCOLS];
    float x2[NCOLS], y2[NCOLS], z2[NCOLS];
#pragma unroll
    for (int k = 0; k < NCOLS; k++) {
        const float* p2 = S2 + ((size_t)b * NQ + (jbase - 1 + k)) * 3;
        x2[k] = p2[0]; y2[k] = p2[1]; z2[k] = p2[2];
    }
    __syncthreads();

    // ---- Column reduction: v[j] = min_i c(i,j) (squared dist; sqrt once). ----
    {
        float mind2[NCOLS]; int mini[NCOLS];
#pragma unroll
        for (int k = 0; k < NCOLS; k++) { mind2[k] = INFV; mini[k] = 0; }
        for (int r = 1; r <= NQ; r++) {
            float4 q = s_pt4[r];
#pragma unroll
            for (int k = 0; k < NCOLS; k++) {
                float dx = q.x - x2[k], dy = q.y - y2[k], dz = q.z - z2[k];
                float d2 = dx * dx + dy * dy + dz * dz;
                if (d2 < mind2[k]) { mind2[k] = d2; mini[k] = r; }
            }
        }
#pragma unroll
        for (int k = 0; k < NCOLS; k++) {
            v[k] = fsqrt_approx(mind2[k]);
            s_way[jbase + k] = mini[k];       // stash argmin row
        }
        __syncthreads();
        if (t == 0) {                          // greedy matching on unique argmins
            for (int j = 1; j <= NQ; j++) {
                int ri = s_way[j];
                if (!s_rowused[ri]) { s_rowused[ri] = 1; s_p[j] = ri; }
            }
            int qt = 0;
            for (int i = 1; i <= NQ; i++)
                if (!s_rowused[i]) s_queue[qt++ & QMASK] = i;
            s_way[0] = qt;
        }
        __syncthreads();
    }

    // ---- Augmenting Row Reduction ----
    {
        int qh = 0, qt = 0, budget = 0;
        if (t == 0) {
            qt = s_way[0];
            budget = 3 * qt + 512;
            int ni = 0;
            if (qh != qt && budget > 0) { ni = s_queue[qh++ & QMASK]; budget--; }
            s_nexti = ni;
        }
        __syncthreads();

        for (;;) {
            const int i = s_nexti;
            if (i == 0) break;
            float4 q = s_pt4[i];

            unsigned long long a1 = ~0ull, a2 = ~0ull;
#pragma unroll
            for (int k = 0; k < NCOLS; k++) {
                float dx = q.x - x2[k], dy = q.y - y2[k], dz = q.z - z2[k];
                float cur = fsqrt_approx(dx * dx + dy * dy + dz * dz) - v[k];
                unsigned long long c =
                    ((unsigned long long)fmap(cur) << 32) | (unsigned)(jbase + k);
                if (c < a1) { a2 = a1; a1 = c; }
                else if (c < a2) a2 = c;
            }
#pragma unroll
            for (int off = 16; off; off >>= 1) {
                unsigned long long b1 = __shfl_down_sync(0xffffffffu, a1, off);
                unsigned long long b2 = __shfl_down_sync(0xffffffffu, a2, off);
                unsigned long long lo = a1 < b1 ? a1 : b1;
                unsigned long long hi = a1 < b1 ? b1 : a1;
                unsigned long long m2 = a2 < b2 ? a2 : b2;
                a1 = lo; a2 = hi < m2 ? hi : m2;
            }
            if (lane == 0) { s_t2[warp][0] = a1; s_t2[warp][1] = a2; }
            __syncthreads();                   // BAR1

            if (t == 0) {
                unsigned long long m1 = ~0ull, m2 = ~0ull;
#pragma unroll
                for (int w = 0; w < NWARP; w++) {
                    unsigned long long b1 = s_t2[w][0], b2 = s_t2[w][1];
                    unsigned long long lo = m1 < b1 ? m1 : b1;
                    unsigned long long hi = m1 < b1 ? b1 : m1;
                    unsigned long long mm = m2 < b2 ? m2 : b2;
                    m1 = lo; m2 = hi < mm ? hi : mm;
                }
                float u1 = funmap((unsigned)(m1 >> 32));
                float u2 = funmap((unsigned)(m2 >> 32));
                int j1c = (int)(m1 & 0xffffffffu);
                int j2c = (int)(m2 & 0xffffffffu);
                int takej; float vadj;
                if (u1 < u2) { takej = j1c; vadj = u2 - u1; }
                else { vadj = 0.0f; takej = (s_p[j1c] != 0) ? j2c : j1c; }
                int i1 = s_p[takej];
                s_p[takej] = i; s_rowused[i] = 1; s_pt4[i].w = u2;
                if (i1 != 0) {
                    s_rowused[i1] = 0; s_pt4[i1].w = 0.0f;
                    s_queue[qt++ & QMASK] = i1;
                }
                int ni = 0;
                if (qh != qt && budget > 0) { ni = s_queue[qh++ & QMASK]; budget--; }
                s_nexti = ni;
                s_takej = takej; s_vadj = vadj;
            }
            __syncthreads();                   // BAR2
            {
                int tj = s_takej;
                if (t == ((tj - 1) >> 3)) v[(tj - 1) & 7] -= s_vadj;
            }
        }
    }

    // ---- Dijkstra augmentation, deferred duals; per-step sync = key polling ----
    unsigned stepcount = 0;                    // uniform across the block
    for (int i = 1; i <= NQ; i++) {
        if (s_rowused[i]) continue;

        float4 q = s_pt4[i];
        float px = q.x, py = q.y, pz = q.z;
        float base = -q.w;                     // base = Dtot - u[i0]; Dtot=0
        float Dtot = 0.0f;
        int   i0 = i, curj0 = 0, used = 0;
        float M[NCOLS], va[NCOLS], ent[NCOLS];
        int   prow[NCOLS];
#pragma unroll
        for (int k = 0; k < NCOLS; k++) { M[k] = INFV; va[k] = -v[k]; }

        int j1f; float Dfin;
        for (;;) {
            // mark the column selected last step as used (enters tree via row i0)
            {
                int tc = curj0 - jbase;
                if (tc >= 0 && tc < NCOLS) {
                    used |= (1 << tc);
                    prow[tc] = i0; ent[tc] = Dtot;
                    M[tc] = INFV; va[tc] += BIGF;   // mask from scan & best
                }
            }

            // scan: independent per-k label updates (no serial best chain)
#pragma unroll
            for (int k = 0; k < NCOLS; k++) {
                float dx = px - x2[k], dy = py - y2[k], dz = pz - z2[k];
                float d = fsqrt_approx(dx * dx + dy * dy + dz * dz);
                float cur = d + base + va[k];
                if (cur < M[k]) { M[k] = cur; s_way[jbase + k] = curj0; }
            }
            // value first: pairwise fminf tree (depth 3)
            float m0 = fminf(M[0], M[1]);
            float m1 = fminf(M[2], M[3]);
            float m2 = fminf(M[4], M[5]);
            float m3 = fminf(M[6], M[7]);
            float bestv = fminf(fminf(m0, m1), fminf(m2, m3));
            unsigned mv = fmap(bestv);
            // index recovery (independent equality mask, overlaps the redux)
            unsigned em = 0;
#pragma unroll
            for (int k = 0; k < NCOLS; k++)
                em |= (M[k] == bestv) ? (1u << k) : 0u;
            int bestj = jbase + (__ffs(em) - 1);

            unsigned wmin = __reduce_min_sync(0xffffffffu, mv);
            unsigned ball = __ballot_sync(0xffffffffu, mv == wmin);
            int src = __ffs((int)ball) - 1;
            int wj = __shfl_sync(0xffffffffu, bestj, src);

            // tagged-key exchange: no block barrier. key = [tag21|val32|j11].
            unsigned tagc = (++stepcount) & TAGM;
            unsigned long long mykey =
                ((unsigned long long)tagc << 43) |
                ((unsigned long long)wmin << 11) | (unsigned)wj;
            if (lane == 0) s_key[stepcount & 1][warp] = mykey;
            unsigned long long key = mykey;
#pragma unroll
            for (int w = 0; w < NWARP; w++) {
                if (w != warp) {
                    unsigned long long o;
                    do { o = s_key[stepcount & 1][w]; }
                    while ((unsigned)(o >> 43) != tagc);
                    if (o < key) key = o;
                }
            }

            int   j1  = (int)(key & 0x7FF);
            float val = funmap((unsigned)((key >> 11) & 0xffffffffu));
            Dtot = val;                        // Delta_new == min label
            int i0n = s_p[j1];
            if (i0n == 0) { j1f = j1; Dfin = val; break; }
            float4 r = s_pt4[i0n];             // entering row untouched this phase
            px = r.x; py = r.y; pz = r.z;
            base = val - r.w;
            i0 = i0n; curj0 = j1;
        }

        // phase-end dual fix-up: each used col's row got (Dfin - ent)
        if (t == 0) s_pt4[i].w += Dfin;        // root in tree the whole phase
#pragma unroll
        for (int k = 0; k < NCOLS; k++) {
            if (used & (1 << k)) {
                float adj = Dfin - ent[k];
                v[k] -= adj;
                s_pt4[prow[k]].w += adj;       // distinct rows: conflict-free
            }
        }
        __syncthreads();
        if (t == 0) {                          // augment alternating path
            int j = j1f;
            while (j != 0) {
                int jn = s_way[j];
                s_p[j] = (jn == 0) ? i : s_p[jn];
                j = jn;
            }
        }
        __syncthreads();
    }
    __syncthreads();

    // ---- Total matched cost ----
    float acc = 0.0f;
#pragma unroll
    for (int k = 0; k < NCOLS; k++) {
        int i0 = s_p[jbase + k];
        float4 q = s_pt4[i0];
        float dx = q.x - x2[k], dy = q.y - y2[k], dz = q.z - z2[k];
        acc += fsqrt_approx(dx * dx + dy * dy + dz * dz);
    }
#pragma unroll
    for (int off = 16; off; off >>= 1)
        acc += __shfl_down_sync(0xffffffffu, acc, off);
    if (lane == 0) s_acc[warp] = acc;
    __syncthreads();
    if (t == 0) {
        float s = 0.0f;
        for (int w = 0; w < NWARP; w++) s += s_acc[w];
        g_partial[b] = s;
        // fused finalize: last CTA to arrive sums and writes the output.
        __threadfence();
        int done = atomicAdd(&g_done, 1);
        if (done == NB - 1) {
            __threadfence();                   // order reads of g_partial after all writes
            float sum = 0.0f;
            for (int bb = 0; bb < NB; bb++) sum += g_partial[bb];
            out[0] = sum / ((float)NQ * (float)NB);
            g_done = 0;                        // reset for next graph replay
        }
    }
}

extern "C" void kernel_launch(void* const* d_in, const int* in_sizes, int n_in,
                              void* d_out, int out_size) {
    const float* S1 = (const float*)d_in[0];
    const float* S2 = (const float*)d_in[1];
    emd_hungarian_kernel<<<NB, NTHREADS>>>(S1, S2, (float*)d_out);
}

// round 16
// speedup vs baseline: 1.5471x; 1.5471x over previous
#include <cuda_runtime.h>
#include <cuda_bf16.h>

#define NTHREADS 128
#define NCOLS 8              // columns per thread (contiguous): 128*8 = 1024
#define NB 8
#define NQ 1024
#define INFV 1e9f
#define BIGF 1e18f
#define NWARP (NTHREADS / 32)
#define QMASK 2047

__device__ float g_partial[NB];
__device__ int   g_done = 0;                  // self-resetting completion counter

__device__ __forceinline__ float fsqrt_approx(float x) {
    float r; asm("sqrt.approx.f32 %0, %1;" : "=f"(r) : "f"(x)); return r;
}
__device__ __forceinline__ unsigned fmap(float x) {
    unsigned u = __float_as_uint(x);
    return (u & 0x80000000u) ? ~u : (u | 0x80000000u);
}
__device__ __forceinline__ float funmap(unsigned m) {
    unsigned u = (m & 0x80000000u) ? (m & 0x7fffffffu) : ~m;
    return __uint_as_float(u);
}
// ---- packed f32x2 helpers (Blackwell FFMA2 path; PTX-only) ----
__device__ __forceinline__ unsigned long long pack2(float lo, float hi) {
    unsigned long long r;
    asm("mov.b64 %0, {%1, %2};" : "=l"(r) : "f"(lo), "f"(hi));
    return r;
}
__device__ __forceinline__ void unpack2(unsigned long long v, float& lo, float& hi) {
    asm("mov.b64 {%0, %1}, %2;" : "=f"(lo), "=f"(hi) : "l"(v));
}
__device__ __forceinline__ unsigned long long add2(unsigned long long a, unsigned long long b) {
    unsigned long long r; asm("add.rn.f32x2 %0, %1, %2;" : "=l"(r) : "l"(a), "l"(b)); return r;
}
__device__ __forceinline__ unsigned long long mul2(unsigned long long a, unsigned long long b) {
    unsigned long long r; asm("mul.rn.f32x2 %0, %1, %2;" : "=l"(r) : "l"(a), "l"(b)); return r;
}
__device__ __forceinline__ unsigned long long fma2(unsigned long long a, unsigned long long b,
                                                   unsigned long long c) {
    unsigned long long r; asm("fma.rn.f32x2 %0, %1, %2, %3;" : "=l"(r) : "l"(a), "l"(b), "l"(c)); return r;
}

__global__ void __launch_bounds__(NTHREADS, 1)
emd_hungarian_kernel(const float* __restrict__ S1, const float* __restrict__ S2,
                     float* __restrict__ out) {
    const int b = blockIdx.x;
    const int t = threadIdx.x;
    const int lane = t & 31;
    const int warp = t >> 5;
    const int jbase = t * NCOLS + 1;          // first owned column (1-based)

    __shared__ float4 s_pt4[NQ + 1];          // row -> {x, y, z, u}
    __shared__ int    s_p[NQ + 1];            // col -> matched row (0 = free)
    __shared__ int    s_way[NQ + 1];
    __shared__ int    s_rowused[NQ + 1];
    __shared__ int    s_queue[QMASK + 1];
    __shared__ __align__(16) unsigned long long s_rk[2][NWARP];
    __shared__ unsigned long long s_t2[NWARP][2];
    __shared__ int    s_nexti, s_takej;
    __shared__ float  s_vadj;
    __shared__ float  s_acc[NWARP];

    for (int r = t; r < NQ; r += NTHREADS) {
        const float* p1 = S1 + ((size_t)b * NQ + r) * 3;
        s_pt4[r + 1] = make_float4(p1[0], p1[1], p1[2], 0.0f);
    }
    for (int idx = t; idx <= NQ; idx += NTHREADS) {
        s_p[idx] = 0; s_rowused[idx] = 0;
    }

    float v[NCOLS];
    float x2[NCOLS], y2[NCOLS], z2[NCOLS];
#pragma unroll
    for (int k = 0; k < NCOLS; k++) {
        const float* p2 = S2 + ((size_t)b * NQ + (jbase - 1 + k)) * 3;
        x2[k] = p2[0]; y2[k] = p2[1]; z2[k] = p2[2];
    }
    // packed negated coords per column pair (constants for the whole solve)
    unsigned long long nx2p[NCOLS / 2], ny2p[NCOLS / 2], nz2p[NCOLS / 2];
#pragma unroll
    for (int h = 0; h < NCOLS / 2; h++) {
        nx2p[h] = pack2(-x2[2 * h], -x2[2 * h + 1]);
        ny2p[h] = pack2(-y2[2 * h], -y2[2 * h + 1]);
        nz2p[h] = pack2(-z2[2 * h], -z2[2 * h + 1]);
    }
    __syncthreads();

    // ---- Column reduction: v[j] = min_i c(i,j) (squared dist; sqrt once). ----
    {
        float mind2[NCOLS]; int mini[NCOLS];
#pragma unroll
        for (int k = 0; k < NCOLS; k++) { mind2[k] = INFV; mini[k] = 0; }
        for (int r = 1; r <= NQ; r++) {
            float4 q = s_pt4[r];
#pragma unroll
            for (int k = 0; k < NCOLS; k++) {
                float dx = q.x - x2[k], dy = q.y - y2[k], dz = q.z - z2[k];
                float d2 = dx * dx + dy * dy + dz * dz;
                if (d2 < mind2[k]) { mind2[k] = d2; mini[k] = r; }
            }
        }
#pragma unroll
        for (int k = 0; k < NCOLS; k++) {
            v[k] = fsqrt_approx(mind2[k]);
            s_way[jbase + k] = mini[k];       // stash argmin row
        }
        __syncthreads();
        if (t == 0) {                          // greedy matching on unique argmins
            for (int j = 1; j <= NQ; j++) {
                int ri = s_way[j];
                if (!s_rowused[ri]) { s_rowused[ri] = 1; s_p[j] = ri; }
            }
            int qt = 0;
            for (int i = 1; i <= NQ; i++)
                if (!s_rowused[i]) s_queue[qt++ & QMASK] = i;
            s_way[0] = qt;
        }
        __syncthreads();
    }

    // ---- Augmenting Row Reduction ----
    {
        int qh = 0, qt = 0, budget = 0;
        if (t == 0) {
            qt = s_way[0];
            budget = 3 * qt + 512;
            int ni = 0;
            if (qh != qt && budget > 0) { ni = s_queue[qh++ & QMASK]; budget--; }
            s_nexti = ni;
        }
        __syncthreads();

        for (;;) {
            const int i = s_nexti;
            if (i == 0) break;
            float4 q = s_pt4[i];

            unsigned long long a1 = ~0ull, a2 = ~0ull;
#pragma unroll
            for (int k = 0; k < NCOLS; k++) {
                float dx = q.x - x2[k], dy = q.y - y2[k], dz = q.z - z2[k];
                float cur = fsqrt_approx(dx * dx + dy * dy + dz * dz) - v[k];
                unsigned long long c =
                    ((unsigned long long)fmap(cur) << 32) | (unsigned)(jbase + k);
                if (c < a1) { a2 = a1; a1 = c; }
                else if (c < a2) a2 = c;
            }
#pragma unroll
            for (int off = 16; off; off >>= 1) {
                unsigned long long b1 = __shfl_down_sync(0xffffffffu, a1, off);
                unsigned long long b2 = __shfl_down_sync(0xffffffffu, a2, off);
                unsigned long long lo = a1 < b1 ? a1 : b1;
                unsigned long long hi = a1 < b1 ? b1 : a1;
                unsigned long long m2 = a2 < b2 ? a2 : b2;
                a1 = lo; a2 = hi < m2 ? hi : m2;
            }
            if (lane == 0) { s_t2[warp][0] = a1; s_t2[warp][1] = a2; }
            __syncthreads();                   // BAR1

            if (t == 0) {
                unsigned long long m1 = ~0ull, m2 = ~0ull;
#pragma unroll
                for (int w = 0; w < NWARP; w++) {
                    unsigned long long b1 = s_t2[w][0], b2 = s_t2[w][1];
                    unsigned long long lo = m1 < b1 ? m1 : b1;
                    unsigned long long hi = m1 < b1 ? b1 : m1;
                    unsigned long long mm = m2 < b2 ? m2 : b2;
                    m1 = lo; m2 = hi < mm ? hi : mm;
                }
                float u1 = funmap((unsigned)(m1 >> 32));
                float u2 = funmap((unsigned)(m2 >> 32));
                int j1c = (int)(m1 & 0xffffffffu);
                int j2c = (int)(m2 & 0xffffffffu);
                int takej; float vadj;
                if (u1 < u2) { takej = j1c; vadj = u2 - u1; }
                else { vadj = 0.0f; takej = (s_p[j1c] != 0) ? j2c : j1c; }
                int i1 = s_p[takej];
                s_p[takej] = i; s_rowused[i] = 1; s_pt4[i].w = u2;
                if (i1 != 0) {
                    s_rowused[i1] = 0; s_pt4[i1].w = 0.0f;
                    s_queue[qt++ & QMASK] = i1;
                }
                int ni = 0;
                if (qh != qt && budget > 0) { ni = s_queue[qh++ & QMASK]; budget--; }
                s_nexti = ni;
                s_takej = takej; s_vadj = vadj;
            }
            __syncthreads();                   // BAR2
            {
                int tj = s_takej;
                if (t == ((tj - 1) >> 3)) v[(tj - 1) & 7] -= s_vadj;
            }
        }
    }

    // ---- Dijkstra augmentation, deferred duals (1 barrier/step) ----
    int sbuf = 0;
    for (int i = 1; i <= NQ; i++) {
        if (s_rowused[i]) continue;

        float4 q = s_pt4[i];
        float px = q.x, py = q.y, pz = q.z;
        float base = -q.w;                     // base = Dtot - u[i0]; Dtot=0
        float Dtot = 0.0f;
        int   i0 = i, curj0 = 0, used = 0;
        float M[NCOLS], va[NCOLS], ent[NCOLS];
        int   prow[NCOLS];
#pragma unroll
        for (int k = 0; k < NCOLS; k++) { M[k] = INFV; va[k] = -v[k]; }

        int j1f; float Dfin;
        for (;;) {
            // mark the column selected last step as used (enters tree via row i0)
            {
                int tc = curj0 - jbase;
                if (tc >= 0 && tc < NCOLS) {
                    used |= (1 << tc);
                    prow[tc] = i0; ent[tc] = Dtot;
                    M[tc] = INFV; va[tc] += BIGF;   // mask from scan & best
                }
            }

            // scan: packed f32x2 distance math (FFMA2), scalar compare/update
            unsigned long long pxp = pack2(px, px);
            unsigned long long pyp = pack2(py, py);
            unsigned long long pzp = pack2(pz, pz);
#pragma unroll
            for (int h = 0; h < NCOLS / 2; h++) {
                unsigned long long dxp = add2(pxp, nx2p[h]);
                unsigned long long dyp = add2(pyp, ny2p[h]);
                unsigned long long dzp = add2(pzp, nz2p[h]);
                unsigned long long s = mul2(dxp, dxp);
                s = fma2(dyp, dyp, s);
                s = fma2(dzp, dzp, s);
                float d2a, d2b; unpack2(s, d2a, d2b);
                const int k0 = 2 * h, k1 = 2 * h + 1;
                float cura = fsqrt_approx(d2a) + base + va[k0];
                float curb = fsqrt_approx(d2b) + base + va[k1];
                if (cura < M[k0]) { M[k0] = cura; s_way[jbase + k0] = curj0; }
                if (curb < M[k1]) { M[k1] = curb; s_way[jbase + k1] = curj0; }
            }
            // value first: pairwise fminf tree (depth 3)
            float m0 = fminf(M[0], M[1]);
            float m1 = fminf(M[2], M[3]);
            float m2 = fminf(M[4], M[5]);
            float m3 = fminf(M[6], M[7]);
            float bestv = fminf(fminf(m0, m1), fminf(m2, m3));
            unsigned mv = fmap(bestv);
            // index recovery (independent equality mask, overlaps the redux)
            unsigned em = 0;
#pragma unroll
            for (int k = 0; k < NCOLS; k++)
                em |= (M[k] == bestv) ? (1u << k) : 0u;
            int bestj = jbase + (__ffs(em) - 1);

            unsigned wmin = __reduce_min_sync(0xffffffffu, mv);
            unsigned ball = __ballot_sync(0xffffffffu, mv == wmin);
            int src = __ffs((int)ball) - 1;
            int wj = __shfl_sync(0xffffffffu, bestj, src);
            if (lane == 0)
                s_rk[sbuf][warp] = ((unsigned long long)wmin << 32) | (unsigned)wj;
            __syncthreads();                   // the ONLY per-step barrier

            const ulonglong2* rk2 = (const ulonglong2*)&s_rk[sbuf][0];
            ulonglong2 k01 = rk2[0], k23 = rk2[1];
            unsigned long long ka = k01.x < k01.y ? k01.x : k01.y;
            unsigned long long kb = k23.x < k23.y ? k23.x : k23.y;
            unsigned long long key = ka < kb ? ka : kb;
            sbuf ^= 1;

            int   j1  = (int)(key & 0xffffffffu);
            float val = funmap((unsigned)(key >> 32));
            Dtot = val;                        // Delta_new == min label
            int i0n = s_p[j1];
            if (i0n == 0) { j1f = j1; Dfin = val; break; }
            float4 r = s_pt4[i0n];             // entering row untouched this phase
            px = r.x; py = r.y; pz = r.z;
            base = val - r.w;
            i0 = i0n; curj0 = j1;
        }

        // phase-end dual fix-up: each used col's row got (Dfin - ent)
        if (t == 0) s_pt4[i].w += Dfin;        // root in tree the whole phase
#pragma unroll
        for (int k = 0; k < NCOLS; k++) {
            if (used & (1 << k)) {
                float adj = Dfin - ent[k];
                v[k] -= adj;
                s_pt4[prow[k]].w += adj;       // distinct rows: conflict-free
            }
        }
        __syncthreads();
        if (t == 0) {                          // augment alternating path
            int j = j1f;
            while (j != 0) {
                int jn = s_way[j];
                s_p[j] = (jn == 0) ? i : s_p[jn];
                j = jn;
            }
        }
        __syncthreads();
    }
    __syncthreads();

    // ---- Total matched cost ----
    float acc = 0.0f;
#pragma unroll
    for (int k = 0; k < NCOLS; k++) {
        int i0 = s_p[jbase + k];
        float4 q = s_pt4[i0];
        float dx = q.x - x2[k], dy = q.y - y2[k], dz = q.z - z2[k];
        acc += fsqrt_approx(dx * dx + dy * dy + dz * dz);
    }
#pragma unroll
    for (int off = 16; off; off >>= 1)
        acc += __shfl_down_sync(0xffffffffu, acc, off);
    if (lane == 0) s_acc[warp] = acc;
    __syncthreads();
    if (t == 0) {
        float s = 0.0f;
        for (int w = 0; w < NWARP; w++) s += s_acc[w];
        g_partial[b] = s;
        // fused finalize: last CTA to arrive sums and writes the output.
        __threadfence();
        int done = atomicAdd(&g_done, 1);
        if (done == NB - 1) {
            __threadfence();                   // order reads of g_partial after all writes
            float sum = 0.0f;
            for (int bb = 0; bb < NB; bb++) sum += g_partial[bb];
            out[0] = sum / ((float)NQ * (float)NB);
            g_done = 0;                        // reset for next graph replay
        }
    }
}

extern "C" void kernel_launch(void* const* d_in, const int* in_sizes, int n_in,
                              void* d_out, int out_size) {
    const float* S1 = (const float*)d_in[0];
    const float* S2 = (const float*)d_in[1];
    emd_hungarian_kernel<<<NB, NTHREADS>>>(S1, S2, (float*)d_out);
}